// round 6
// baseline (speedup 1.0000x reference)
#include <cuda_runtime.h>
#include <cstddef>

// Fixed shapes: B=4, C=16, H=W=512
#define BB 4
#define CC 16
#define HH 512
#define WW 512
#define NN (HH * WW)
#define NPLANES (BB * CC)       // 64
#define E_CNT 2091012

#define RY 4                    // rows per warp strip
#define TP 258                  // transpose smem pitch (conflict-free)

// ---------------------------------------------------------------------------
// edge_start: analytic offset of node (h,w)'s first edge in reference order.
// ---------------------------------------------------------------------------
__device__ __forceinline__ int edge_start(int h, int w) {
    int R  = (h == 0) ? 0 : 2556 + (h - 1) * 4090;
    int vh = (h == 0 || h == HH - 1) ? 2 : 3;
    int Sv = (w == 0) ? 0 : 3 * w - 1;
    return R + vh * Sv - w;
}

// ---------------------------------------------------------------------------
// Kernel 1: NCHW -> (B*H*W, C) via smem staging. Coalesced loads AND stores.
// ---------------------------------------------------------------------------
__global__ void __launch_bounds__(256) transpose_kernel(const float* __restrict__ in,
                                                        float* __restrict__ out) {
    __shared__ float s[CC * TP];

    int t  = threadIdx.x;
    int p0 = blockIdx.x * 256;
    int b  = blockIdx.y;

    const float* src = in + (size_t)b * CC * NN + p0 + t;
#pragma unroll
    for (int c = 0; c < CC; c++)
        s[c * TP + t] = src[(size_t)c * NN];
    __syncthreads();

    float4* o = (float4*)(out + ((size_t)b * NN + p0) * CC);
    int ch = (t & 3) * 4;
#pragma unroll
    for (int i = 0; i < 4; i++) {
        int px = i * 64 + (t >> 2);
        o[i * 256 + t] = make_float4(s[(ch + 0) * TP + px],
                                     s[(ch + 1) * TP + px],
                                     s[(ch + 2) * TP + px],
                                     s[(ch + 3) * TP + px]);
    }
}

// ---------------------------------------------------------------------------
// Per-pixel edge emission (both directions of each undirected pair).
// ---------------------------------------------------------------------------
__device__ __forceinline__ void emit_edges(int x, int y,
                                           float f0, float f1, float f2, float f3,
                                           float* __restrict__ eio,
                                           float2* __restrict__ attr) {
    const float SQ2 = 1.41421356237309515f;
    int p = (y << 9) | x;

    int Sp = edge_start(y, x);
    int posE  = ((y > 0) & (x > 0)) + (y > 0) + ((y > 0) & (x < WW - 1)) + (x > 0);
    int posSW = posE + (x < WW - 1);
    int posS  = posSW + ((y < HH - 1) & (x > 0));
    int posSE = posS + (y < HH - 1);

    float* ei_dst = eio + E_CNT;
    float fp = (float)p;

    if (x < WW - 1) {  // E ; reverse (0,-1) at (y, x+1)
        int q = p + 1;
        int er = edge_start(y, x + 1) + ((y > 0) ? (2 + (x < WW - 2)) : 0);
        int ef = Sp + posE;
        float2 a = make_float2(1.0f, f0);
        attr[ef] = a; attr[er] = a;
        eio[ef] = fp;        ei_dst[ef] = (float)q;
        eio[er] = (float)q;  ei_dst[er] = fp;
    }
    if (y < HH - 1 && x > 0) {  // SW ; reverse (-1,1) at (y+1, x-1)
        int q = p + WW - 1;
        int er = edge_start(y + 1, x - 1) + 1 + (x > 1);
        int ef = Sp + posSW;
        float2 a = make_float2(SQ2, f1);
        attr[ef] = a; attr[er] = a;
        eio[ef] = fp;        ei_dst[ef] = (float)q;
        eio[er] = (float)q;  ei_dst[er] = fp;
    }
    if (y < HH - 1) {  // S ; reverse (-1,0) at (y+1, x)
        int q = p + WW;
        int er = edge_start(y + 1, x) + (x > 0);
        int ef = Sp + posS;
        float2 a = make_float2(1.0f, f2);
        attr[ef] = a; attr[er] = a;
        eio[ef] = fp;        ei_dst[ef] = (float)q;
        eio[er] = (float)q;  ei_dst[er] = fp;
    }
    if (y < HH - 1 && x < WW - 1) {  // SE ; reverse (-1,-1) at (y+1, x+1)
        int q = p + WW + 1;
        int er = edge_start(y + 1, x + 1);
        int ef = Sp + posSE;
        float2 a = make_float2(SQ2, f3);
        attr[ef] = a; attr[er] = a;
        eio[ef] = fp;        ei_dst[ef] = (float)q;
        eio[er] = (float)q;  ei_dst[er] = fp;
    }
}

// ---------------------------------------------------------------------------
// Kernel 2: warp-autonomous rolling-row edge kernel. No smem, no barriers.
// Warp = 32 cols x RY rows. cur row of all 64 planes lives in registers;
// next row loaded in 8-wide batches (MLP=8); x+-1 via shuffles; warp-edge
// lanes via one predicated boundary load. E-diff of row y+1 is computed
// from row-y's shuffled values (rolling accumulator).
// ---------------------------------------------------------------------------
__global__ void __launch_bounds__(128, 4) edge_kernel(const float* __restrict__ grid,
                                                      float* __restrict__ eio,
                                                      float2* __restrict__ attr) {
    const unsigned FULL = 0xffffffffu;
    int warp = blockIdx.x * 4 + (threadIdx.x >> 5);
    int lane = threadIdx.x & 31;

    int cchunk = warp & 15;          // 16 column chunks
    int rchunk = warp >> 4;          // 128 row chunks
    int cx = cchunk * 32;
    int y0 = rchunk * RY;
    int x  = cx + lane;

    bool isL = (lane == 0), isR = (lane == 31);
    bool bl  = isL || isR;
    int xb   = isL ? max(cx - 1, 0) : min(cx + 32, WW - 1);
    int xbR  = min(cx + 32, WW - 1);

    const float inv = 1.0f / (float)NPLANES;

    float cur[NPLANES];
    float aE = 0.f;

    // ---- prologue: load row y0 of all planes; compute E(y0) ----
    {
        int ro = y0 * WW;
#pragma unroll
        for (int jb = 0; jb < 8; jb++) {
            float t[8], tb[8];
#pragma unroll
            for (int u = 0; u < 8; u++) {
                const float* pl = grid + (size_t)(jb * 8 + u) * NN;
                t[u] = pl[ro + x];
                if (isR) tb[u] = pl[ro + xbR];
            }
#pragma unroll
            for (int u = 0; u < 8; u++) {
                float cdn = __shfl_down_sync(FULL, t[u], 1);
                if (isR) cdn = tb[u];
                aE += fabsf(t[u] - cdn);
                cur[jb * 8 + u] = t[u];
            }
        }
    }

    // ---- main: RY rows ----
#pragma unroll
    for (int r = 0; r < RY; r++) {
        int y  = y0 + r;
        int y1 = min(y + 1, HH - 1);
        int ro = y1 * WW;

        float a1 = 0.f, a2 = 0.f, a3 = 0.f, aEn = 0.f;
#pragma unroll
        for (int jb = 0; jb < 8; jb++) {
            float t[8], tb[8];
#pragma unroll
            for (int u = 0; u < 8; u++) {
                const float* pl = grid + (size_t)(jb * 8 + u) * NN;
                t[u] = pl[ro + x];
                if (bl) tb[u] = pl[ro + xb];
            }
#pragma unroll
            for (int u = 0; u < 8; u++) {
                float nv  = t[u];
                float sup = __shfl_up_sync(FULL, nv, 1);    // nxt(x-1)
                float sdn = __shfl_down_sync(FULL, nv, 1);  // nxt(x+1)
                if (isL) sup = tb[u];
                if (isR) sdn = tb[u];
                float cv = cur[jb * 8 + u];
                a1  += fabsf(cv - sup);   // SW
                a2  += fabsf(cv - nv);    // S
                a3  += fabsf(cv - sdn);   // SE
                aEn += fabsf(nv - sdn);   // E of row y+1
                cur[jb * 8 + u] = nv;
            }
        }

        emit_edges(x, y, aE * inv, a1 * inv, a2 * inv, a3 * inv, eio, attr);
        aE = aEn;
    }
}

// ---------------------------------------------------------------------------
extern "C" void kernel_launch(void* const* d_in, const int* in_sizes, int n_in,
                              void* d_out, int out_size) {
    const float* grid = (const float*)d_in[0];

    float* out   = (float*)d_out;
    float* nf    = out;
    float* eio   = out + (size_t)BB * NN * CC;
    float2* attr = (float2*)(eio + 2 * E_CNT);

    transpose_kernel<<<dim3(NN / 256, BB), 256>>>(grid, nf);
    // 2048 warps = 512 blocks of 128 threads
    edge_kernel<<<512, 128>>>(grid, eio, attr);
}